// round 4
// baseline (speedup 1.0000x reference)
#include <cuda_runtime.h>
#include <cstdint>

#define N_NODES 100000
#define N_EDGES 1600000
#define D 128
#define SCAN_BLK 1024
#define N_SCAN_BLKS ((N_NODES + SCAN_BLK - 1) / SCAN_BLK)   // 98

// ---------------- device-global scratch (no allocation allowed) ----------------
__device__ float g_h[(size_t)N_NODES * D];   // x @ W
__device__ float g_dinv[N_NODES];            // deg^{-1/2} over src endpoints
__device__ int   g_degs[N_NODES];            // histogram of src
__device__ int   g_cntd[N_NODES];            // histogram of dst (bucket sizes)
__device__ int   g_cur[N_NODES];             // bucket cursors
__device__ int   g_offp[N_NODES];            // per-block exclusive scan partials
__device__ int   g_off[N_NODES];             // global exclusive offsets
__device__ int   g_bsums[SCAN_BLK];          // scan block sums (98 used)
__device__ int   g_esrc[N_EDGES];            // src ids bucketed by dst

// ---------- packed f32x2 helpers (Blackwell fma.rn.f32x2: 2x fp32 FMA rate) ----------
__device__ __forceinline__ unsigned long long pack2(float a, float b) {
    unsigned long long r;
    asm("mov.b64 %0, {%1, %2};" : "=l"(r) : "r"(__float_as_uint(a)), "r"(__float_as_uint(b)));
    return r;
}
__device__ __forceinline__ unsigned long long fma2(unsigned long long a,
                                                   unsigned long long b,
                                                   unsigned long long c) {
    unsigned long long d;
    asm("fma.rn.f32x2 %0, %1, %2, %3;" : "=l"(d) : "l"(a), "l"(b), "l"(c));
    return d;
}
__device__ __forceinline__ void unpack2(unsigned long long v, float& lo, float& hi) {
    unsigned int l, h;
    asm("mov.b64 {%0, %1}, %2;" : "=r"(l), "=r"(h) : "l"(v));
    lo = __uint_as_float(l);
    hi = __uint_as_float(h);
}

// ---------- 1) zero the int scratch ----------
__global__ void k_zero() {
    int i = blockIdx.x * blockDim.x + threadIdx.x;
    if (i < N_NODES) {
        g_degs[i] = 0;
        g_cntd[i] = 0;
        g_cur[i]  = 0;
    }
}

// ---------- 2) histograms: deg over src, bucket counts over dst ----------
__global__ void k_count(const int* __restrict__ ei) {
    int e = blockIdx.x * blockDim.x + threadIdx.x;
    if (e < N_EDGES) {
        int s = ei[e];             // edge_index[0][e]
        int d = ei[N_EDGES + e];   // edge_index[1][e]
        atomicAdd(&g_degs[s], 1);
        atomicAdd(&g_cntd[d], 1);
    }
}

// ---------- 3) dinv = deg > 0 ? rsqrt(deg) : 0 ----------
__global__ void k_dinv() {
    int i = blockIdx.x * blockDim.x + threadIdx.x;
    if (i < N_NODES) {
        int d = g_degs[i];
        g_dinv[i] = (d > 0) ? rsqrtf((float)d) : 0.0f;
    }
}

// ---------- 4) exclusive scan of g_cntd -> g_off (3 kernels) ----------
__global__ void k_scan1() {
    __shared__ int s[SCAN_BLK];
    int tid = threadIdx.x;
    int i = blockIdx.x * SCAN_BLK + tid;
    int v = (i < N_NODES) ? g_cntd[i] : 0;
    s[tid] = v;
    __syncthreads();
    #pragma unroll
    for (int o = 1; o < SCAN_BLK; o <<= 1) {
        int t = (tid >= o) ? s[tid - o] : 0;
        __syncthreads();
        s[tid] += t;
        __syncthreads();
    }
    if (i < N_NODES) g_offp[i] = s[tid] - v;   // exclusive
    if (tid == SCAN_BLK - 1) g_bsums[blockIdx.x] = s[tid];
}

__global__ void k_scan2() {
    __shared__ int s[SCAN_BLK];
    int tid = threadIdx.x;
    int v = (tid < N_SCAN_BLKS) ? g_bsums[tid] : 0;
    s[tid] = v;
    __syncthreads();
    #pragma unroll
    for (int o = 1; o < SCAN_BLK; o <<= 1) {
        int t = (tid >= o) ? s[tid - o] : 0;
        __syncthreads();
        s[tid] += t;
        __syncthreads();
    }
    if (tid < N_SCAN_BLKS) g_bsums[tid] = s[tid] - v;   // exclusive
}

__global__ void k_scan3() {
    int i = blockIdx.x * blockDim.x + threadIdx.x;
    if (i < N_NODES) g_off[i] = g_offp[i] + g_bsums[i >> 10];
}

// ---------- 5) bucket edges by dst (int atomics only) ----------
__global__ void k_bucket(const int* __restrict__ ei) {
    int e = blockIdx.x * blockDim.x + threadIdx.x;
    if (e < N_EDGES) {
        int s = ei[e];
        int d = ei[N_EDGES + e];
        int pos = atomicAdd(&g_cur[d], 1);
        g_esrc[g_off[d] + pos] = s;
    }
}

// ---------- 6) GEMM: g_h = x @ W  (fp32, f32x2-packed FFMA) ----------
__global__ void k_gemm(const float* __restrict__ x, const float* __restrict__ w) {
    extern __shared__ float sm[];
    float* ws = sm;            // [128][128]
    float* xs = sm + D * D;    // [64][128]

    const int tid = threadIdx.x;
    const int row0 = blockIdx.x * 64;

    {
        float4* ws4 = (float4*)ws;
        const float4* w4 = (const float4*)w;
        #pragma unroll
        for (int i = tid; i < D * D / 4; i += 256) ws4[i] = w4[i];
    }
    {
        float4* xs4 = (float4*)xs;
        const float4* x4 = (const float4*)x;
        #pragma unroll
        for (int i = tid; i < 64 * D / 4; i += 256) {
            int r = i >> 5;
            int gr = row0 + r;
            xs4[i] = (gr < N_NODES) ? x4[(size_t)gr * (D / 4) + (i & 31)]
                                    : make_float4(0.f, 0.f, 0.f, 0.f);
        }
    }
    __syncthreads();

    const int col_t = tid & 31;   // float4 column group
    const int row_t = tid >> 5;   // 8-row group (constant within warp -> xs broadcast)

    unsigned long long acc[8][2];
    #pragma unroll
    for (int i = 0; i < 8; i++) { acc[i][0] = 0ull; acc[i][1] = 0ull; }

    const float* xbase = xs + row_t * 8 * D;

    #pragma unroll 4
    for (int k = 0; k < D; k++) {
        float4 wv = *(const float4*)(ws + k * D + col_t * 4);   // conflict-free LDS.128
        unsigned long long w01 = pack2(wv.x, wv.y);
        unsigned long long w23 = pack2(wv.z, wv.w);
        const float* xp = xbase + k;
        #pragma unroll
        for (int i = 0; i < 8; i++) {
            float xv = xp[i * D];                               // broadcast LDS
            unsigned long long xx = pack2(xv, xv);
            acc[i][0] = fma2(xx, w01, acc[i][0]);
            acc[i][1] = fma2(xx, w23, acc[i][1]);
        }
    }

    #pragma unroll
    for (int i = 0; i < 8; i++) {
        int row = row0 + row_t * 8 + i;
        if (row < N_NODES) {
            float a, b, c, d;
            unpack2(acc[i][0], a, b);
            unpack2(acc[i][1], c, d);
            *(float4*)(g_h + (size_t)row * D + col_t * 4) = make_float4(a, b, c, d);
        }
    }
}

// ---------- 7) gather: out[n] = bias + sum_{e in bucket(n)} dinv[s]*dinv[n]*h[s] ----------
__global__ void k_gather(const float* __restrict__ bias, float* __restrict__ out) {
    int n = (blockIdx.x * blockDim.x + threadIdx.x) >> 5;
    int lane = threadIdx.x & 31;
    if (n >= N_NODES) return;

    int off = g_off[n];
    int cnt = g_cntd[n];
    float dn = g_dinv[n];

    float4 acc = *(const float4*)(bias + lane * 4);   // fold bias into init

    int i = 0;
    for (; i + 1 < cnt; i += 2) {                     // 2-edge ILP
        int s0 = g_esrc[off + i];
        int s1 = g_esrc[off + i + 1];
        float n0 = dn * g_dinv[s0];
        float n1 = dn * g_dinv[s1];
        float4 h0 = *(const float4*)(g_h + (size_t)s0 * D + lane * 4);
        float4 h1 = *(const float4*)(g_h + (size_t)s1 * D + lane * 4);
        acc.x += n0 * h0.x + n1 * h1.x;
        acc.y += n0 * h0.y + n1 * h1.y;
        acc.z += n0 * h0.z + n1 * h1.z;
        acc.w += n0 * h0.w + n1 * h1.w;
    }
    if (i < cnt) {
        int s0 = g_esrc[off + i];
        float n0 = dn * g_dinv[s0];
        float4 h0 = *(const float4*)(g_h + (size_t)s0 * D + lane * 4);
        acc.x += n0 * h0.x;
        acc.y += n0 * h0.y;
        acc.z += n0 * h0.z;
        acc.w += n0 * h0.w;
    }

    *(float4*)(out + (size_t)n * D + lane * 4) = acc;   // streamed, atomic-free
}

extern "C" void kernel_launch(void* const* d_in, const int* in_sizes, int n_in,
                              void* d_out, int out_size) {
    const float* x    = (const float*)d_in[0];
    const int*   ei   = (const int*)d_in[1];     // int32: JAX x64-disabled downcasts int64
    const float* w    = (const float*)d_in[2];
    const float* bias = (const float*)d_in[3];
    float*       out  = (float*)d_out;

    const int smem_gemm = (D * D + 64 * D) * (int)sizeof(float);  // 96 KB
    cudaFuncSetAttribute(k_gemm, cudaFuncAttributeMaxDynamicSharedMemorySize, smem_gemm);

    k_zero  <<<(N_NODES + 255) / 256, 256>>>();
    k_count <<<(N_EDGES + 255) / 256, 256>>>(ei);
    k_dinv  <<<(N_NODES + 255) / 256, 256>>>();
    k_scan1 <<<N_SCAN_BLKS, SCAN_BLK>>>();
    k_scan2 <<<1, SCAN_BLK>>>();
    k_scan3 <<<(N_NODES + 255) / 256, 256>>>();
    k_bucket<<<(N_EDGES + 255) / 256, 256>>>(ei);
    k_gemm  <<<(N_NODES + 63) / 64, 256, smem_gemm>>>(x, w);
    k_gather<<<(N_NODES * 32 + 255) / 256, 256>>>(bias, out);
}

// round 6
// speedup vs baseline: 1.2405x; 1.2405x over previous
#include <cuda_runtime.h>
#include <cuda_bf16.h>
#include <cstdint>

#define N_NODES 100000
#define N_EDGES 1600000
#define D 128
#define SCAN_BLK 1024
#define N_SCAN_BLKS ((N_NODES + SCAN_BLK - 1) / SCAN_BLK)   // 98

// ---------------- device-global scratch ----------------
__device__ float g_h[(size_t)N_NODES * D];   // dinv[n] * (x @ W)[n]
__device__ float g_dinv[N_NODES];
__device__ int   g_degs[N_NODES];
__device__ int   g_cntd[N_NODES];
__device__ int   g_cur[N_NODES];             // bucket cursors (absolute)
__device__ int   g_offp[N_NODES];
__device__ int   g_off[N_NODES];
__device__ int   g_bsums[SCAN_BLK];
__device__ int   g_esrc[N_EDGES];

__device__ __forceinline__ uint32_t smem_u32(const void* p) {
    uint32_t a;
    asm("{ .reg .u64 t; cvta.to.shared.u64 t, %1; cvt.u32.u64 %0, t; }" : "=r"(a) : "l"(p));
    return a;
}
__device__ __forceinline__ void ldm4(uint32_t* r, uint32_t addr) {
    asm volatile("ldmatrix.sync.aligned.m8n8.x4.shared.b16 {%0,%1,%2,%3}, [%4];"
                 : "=r"(r[0]), "=r"(r[1]), "=r"(r[2]), "=r"(r[3]) : "r"(addr));
}
__device__ __forceinline__ void mma_bf16(float* c, const uint32_t* a, uint32_t b0, uint32_t b1) {
    asm volatile("mma.sync.aligned.m16n8k16.row.col.f32.bf16.bf16.f32 "
                 "{%0,%1,%2,%3}, {%4,%5,%6,%7}, {%8,%9}, {%0,%1,%2,%3};"
                 : "+f"(c[0]), "+f"(c[1]), "+f"(c[2]), "+f"(c[3])
                 : "r"(a[0]), "r"(a[1]), "r"(a[2]), "r"(a[3]), "r"(b0), "r"(b1));
}

// ---------- 1) zero int scratch ----------
__global__ void k_zero() {
    int i = blockIdx.x * blockDim.x + threadIdx.x;
    if (i < N_NODES) { g_degs[i] = 0; g_cntd[i] = 0; }
}

// ---------- 2) histograms (2 edges/thread via int2) ----------
__global__ void k_count(const int* __restrict__ ei) {
    int t = blockIdx.x * blockDim.x + threadIdx.x;
    if (t < N_EDGES / 2) {
        int2 s = ((const int2*)ei)[t];
        int2 d = ((const int2*)(ei + N_EDGES))[t];
        atomicAdd(&g_degs[s.x], 1); atomicAdd(&g_degs[s.y], 1);
        atomicAdd(&g_cntd[d.x], 1); atomicAdd(&g_cntd[d.y], 1);
    }
}

// ---------- 3) dinv ----------
__global__ void k_dinv() {
    int i = blockIdx.x * blockDim.x + threadIdx.x;
    if (i < N_NODES) {
        int d = g_degs[i];
        g_dinv[i] = (d > 0) ? rsqrtf((float)d) : 0.0f;
    }
}

// ---------- 4) exclusive scan of g_cntd -> g_off ----------
__global__ void k_scan1() {
    __shared__ int s[SCAN_BLK];
    int tid = threadIdx.x;
    int i = blockIdx.x * SCAN_BLK + tid;
    int v = (i < N_NODES) ? g_cntd[i] : 0;
    s[tid] = v;
    __syncthreads();
    #pragma unroll
    for (int o = 1; o < SCAN_BLK; o <<= 1) {
        int t = (tid >= o) ? s[tid - o] : 0;
        __syncthreads();
        s[tid] += t;
        __syncthreads();
    }
    if (i < N_NODES) g_offp[i] = s[tid] - v;
    if (tid == SCAN_BLK - 1) g_bsums[blockIdx.x] = s[tid];
}
__global__ void k_scan2() {
    __shared__ int s[SCAN_BLK];
    int tid = threadIdx.x;
    int v = (tid < N_SCAN_BLKS) ? g_bsums[tid] : 0;
    s[tid] = v;
    __syncthreads();
    #pragma unroll
    for (int o = 1; o < SCAN_BLK; o <<= 1) {
        int t = (tid >= o) ? s[tid - o] : 0;
        __syncthreads();
        s[tid] += t;
        __syncthreads();
    }
    if (tid < N_SCAN_BLKS) g_bsums[tid] = s[tid] - v;
}
__global__ void k_scan3() {
    int i = blockIdx.x * blockDim.x + threadIdx.x;
    if (i < N_NODES) {
        int o = g_offp[i] + g_bsums[i >> 10];
        g_off[i] = o;
        g_cur[i] = o;
    }
}

// ---------- 5) bucket edges by dst ----------
__global__ void k_bucket(const int* __restrict__ ei) {
    int e = blockIdx.x * blockDim.x + threadIdx.x;
    if (e < N_EDGES) {
        int s = ei[e];
        int d = ei[N_EDGES + e];
        int pos = atomicAdd(&g_cur[d], 1);
        g_esrc[pos] = s;
    }
}

// ---------- 6) HMMA bf16x3 GEMM: g_h = dinv .* (x @ W) ----------
// CTA: 256 rows x 128 cols, 512 threads (16 warps, 8x2 warp grid, 32x64 per warp).
// A (x rows) and B (= W^T, [n][k]) staged as bf16 hi+lo in smem, stride 136
// halves (272B rows -> conflict-free ldmatrix). 3 products: AhBh + AhBl + AlBh.
#define KS 136                       // smem row stride in halves
#define ROWB (KS * 2)                // 272 bytes
#define OFF_AH 0
#define OFF_AL (256 * ROWB)          // 69632
#define OFF_BH (2 * 256 * ROWB)      // 139264
#define OFF_BL (OFF_BH + 128 * ROWB) // 174080
#define SM_TOTAL (OFF_BL + 128 * ROWB)  // 208896

__global__ void __launch_bounds__(512, 1)
k_gemm(const float* __restrict__ x, const float* __restrict__ w) {
    extern __shared__ __align__(16) char smem[];
    const int tid = threadIdx.x;
    const int lane = tid & 31;
    const int wid = tid >> 5;
    const int row0 = blockIdx.x * 256;

    // ---- stage A: 256 rows x 128 cols, hi+lo bf16 ----
    #pragma unroll
    for (int i = tid; i < 4096; i += 512) {
        int r = i >> 4, c8 = i & 15;
        int gr = row0 + r;
        float4 v0 = make_float4(0.f, 0.f, 0.f, 0.f), v1 = v0;
        if (gr < N_NODES) {
            const float4* xp = (const float4*)(x + (size_t)gr * D + c8 * 8);
            v0 = xp[0]; v1 = xp[1];
        }
        float f[8] = {v0.x, v0.y, v0.z, v0.w, v1.x, v1.y, v1.z, v1.w};
        uint32_t hi[4], lo[4];
        #pragma unroll
        for (int j = 0; j < 4; j++) {
            float a = f[2 * j], b = f[2 * j + 1];
            __nv_bfloat16 ha = __float2bfloat16_rn(a), hb = __float2bfloat16_rn(b);
            float la = a - __bfloat162float(ha), lb = b - __bfloat162float(hb);
            __nv_bfloat16 hla = __float2bfloat16_rn(la), hlb = __float2bfloat16_rn(lb);
            hi[j] = ((uint32_t)__bfloat16_as_ushort(hb) << 16) | __bfloat16_as_ushort(ha);
            lo[j] = ((uint32_t)__bfloat16_as_ushort(hlb) << 16) | __bfloat16_as_ushort(hla);
        }
        char* pa = smem + r * ROWB + c8 * 16;
        *(uint4*)(pa + OFF_AH) = make_uint4(hi[0], hi[1], hi[2], hi[3]);
        *(uint4*)(pa + OFF_AL) = make_uint4(lo[0], lo[1], lo[2], lo[3]);
    }

    // ---- stage B = W^T: [n][k], hi+lo bf16 (coalesced w read) ----
    #pragma unroll
    for (int i = tid; i < 16384; i += 512) {
        int k = i >> 7, n = i & 127;
        float wv = w[i];                      // w[k*128 + n]
        __nv_bfloat16 hb = __float2bfloat16_rn(wv);
        __nv_bfloat16 lb = __float2bfloat16_rn(wv - __bfloat162float(hb));
        int off = n * ROWB + k * 2;
        *(__nv_bfloat16*)(smem + OFF_BH + off) = hb;
        *(__nv_bfloat16*)(smem + OFF_BL + off) = lb;
    }
    __syncthreads();

    const uint32_t sbase = smem_u32(smem);
    const int wm = (wid >> 1) * 32;           // warp row base (0..224)
    const int wn = (wid & 1) * 64;            // warp col base (0 or 64)

    // per-lane ldmatrix base offsets (bytes)
    const uint32_t aoff = sbase + (uint32_t)((wm + (lane & 15)) * ROWB + (lane >> 4) * 16);
    const uint32_t boff = sbase + (uint32_t)((wn + (lane & 15)) * ROWB + (lane >> 4) * 16);

    float acc[2][8][4];
    #pragma unroll
    for (int a = 0; a < 2; a++)
        #pragma unroll
        for (int b = 0; b < 8; b++)
            #pragma unroll
            for (int c = 0; c < 4; c++) acc[a][b][c] = 0.0f;

    #pragma unroll
    for (int ks = 0; ks < 8; ks++) {
        const uint32_t kb = ks * 32;          // 16 halves = 32 bytes
        uint32_t ah[2][4], al[2][4];
        #pragma unroll
        for (int mi = 0; mi < 2; mi++) {
            ldm4(ah[mi], aoff + OFF_AH + mi * 16 * ROWB + kb);
            ldm4(al[mi], aoff + OFF_AL + mi * 16 * ROWB + kb);
        }
        #pragma unroll
        for (int pj = 0; pj < 4; pj++) {      // pair of n-atoms (16 cols)
            uint32_t bh[4], bl[4];
            ldm4(bh, boff + OFF_BH + pj * 16 * ROWB + kb);
            ldm4(bl, boff + OFF_BL + pj * 16 * ROWB + kb);
            #pragma unroll
            for (int mi = 0; mi < 2; mi++) {
                mma_bf16(acc[mi][pj * 2],     ah[mi], bh[0], bh[2]);
                mma_bf16(acc[mi][pj * 2],     ah[mi], bl[0], bl[2]);
                mma_bf16(acc[mi][pj * 2],     al[mi], bh[0], bh[2]);
                mma_bf16(acc[mi][pj * 2 + 1], ah[mi], bh[1], bh[3]);
                mma_bf16(acc[mi][pj * 2 + 1], ah[mi], bl[1], bl[3]);
                mma_bf16(acc[mi][pj * 2 + 1], al[mi], bh[1], bh[3]);
            }
        }
    }

    // ---- epilogue: scale rows by dinv, store fp32 ----
    #pragma unroll
    for (int mi = 0; mi < 2; mi++) {
        int rl = row0 + wm + mi * 16 + (lane >> 2);
        int rh = rl + 8;
        float dvl = (rl < N_NODES) ? g_dinv[rl] : 0.0f;
        float dvh = (rh < N_NODES) ? g_dinv[rh] : 0.0f;
        #pragma unroll
        for (int nj = 0; nj < 8; nj++) {
            int col = wn + nj * 8 + (lane & 3) * 2;
            if (rl < N_NODES)
                *(float2*)(g_h + (size_t)rl * D + col) =
                    make_float2(dvl * acc[mi][nj][0], dvl * acc[mi][nj][1]);
            if (rh < N_NODES)
                *(float2*)(g_h + (size_t)rh * D + col) =
                    make_float2(dvh * acc[mi][nj][2], dvh * acc[mi][nj][3]);
        }
    }
}

// ---------- 7) gather: out[n] = bias + dinv[n] * sum_{s in bucket(n)} g_h[s] ----------
__global__ void k_gather(const float* __restrict__ bias, float* __restrict__ out) {
    int n = (blockIdx.x * blockDim.x + threadIdx.x) >> 5;
    int lane = threadIdx.x & 31;
    if (n >= N_NODES) return;

    int off = g_off[n];
    int cnt = g_cntd[n];
    float dn = g_dinv[n];

    float4 acc = make_float4(0.f, 0.f, 0.f, 0.f);
    int i = 0;
    for (; i + 4 <= cnt; i += 4) {
        int s0 = g_esrc[off + i], s1 = g_esrc[off + i + 1];
        int s2 = g_esrc[off + i + 2], s3 = g_esrc[off + i + 3];
        float4 h0 = *(const float4*)(g_h + (size_t)s0 * D + lane * 4);
        float4 h1 = *(const float4*)(g_h + (size_t)s1 * D + lane * 4);
        float4 h2 = *(const float4*)(g_h + (size_t)s2 * D + lane * 4);
        float4 h3 = *(const float4*)(g_h + (size_t)s3 * D + lane * 4);
        acc.x += (h0.x + h1.x) + (h2.x + h3.x);
        acc.y += (h0.y + h1.y) + (h2.y + h3.y);
        acc.z += (h0.z + h1.z) + (h2.z + h3.z);
        acc.w += (h0.w + h1.w) + (h2.w + h3.w);
    }
    for (; i < cnt; i++) {
        int s0 = g_esrc[off + i];
        float4 h0 = *(const float4*)(g_h + (size_t)s0 * D + lane * 4);
        acc.x += h0.x; acc.y += h0.y; acc.z += h0.z; acc.w += h0.w;
    }

    float4 b = ((const float4*)bias)[lane];
    *(float4*)(out + (size_t)n * D + lane * 4) =
        make_float4(b.x + dn * acc.x, b.y + dn * acc.y, b.z + dn * acc.z, b.w + dn * acc.w);
}

extern "C" void kernel_launch(void* const* d_in, const int* in_sizes, int n_in,
                              void* d_out, int out_size) {
    const float* x    = (const float*)d_in[0];
    const int*   ei   = (const int*)d_in[1];
    const float* w    = (const float*)d_in[2];
    const float* bias = (const float*)d_in[3];
    float*       out  = (float*)d_out;

    cudaFuncSetAttribute(k_gemm, cudaFuncAttributeMaxDynamicSharedMemorySize, SM_TOTAL);

    k_zero  <<<(N_NODES + 255) / 256, 256>>>();
    k_count <<<(N_EDGES / 2 + 255) / 256, 256>>>(ei);
    k_dinv  <<<(N_NODES + 255) / 256, 256>>>();
    k_scan1 <<<N_SCAN_BLKS, SCAN_BLK>>>();
    k_scan2 <<<1, SCAN_BLK>>>();
    k_scan3 <<<(N_NODES + 255) / 256, 256>>>();
    k_bucket<<<(N_EDGES + 255) / 256, 256>>>(ei);
    k_gemm  <<<(N_NODES + 255) / 256, 512, SM_TOTAL>>>(x, w);
    k_gather<<<(N_NODES * 32 + 255) / 256, 256>>>(bias, out);
}